// round 16
// baseline (speedup 1.0000x reference)
#include <cuda_runtime.h>
#include <stdint.h>
#include <math.h>

#define PI_F 3.14159274101257324f
typedef unsigned long long ull;

static __device__ float  g_C [512*512];
static __device__ float  g_Ct[512*512];
static __device__ float4 g_G [512*512];
static __device__ float  g_F [512*512];
static __device__ float  g_W [512*1024];
static __device__ float  g_W2[512*1024];
static __device__ float2 g_part[2][64];
static __device__ float  g_std[2];

__device__ __forceinline__ ull fpack(float lo, float hi) {
    ull p;
    asm("mov.b64 %0, {%1, %2};" : "=l"(p) : "r"(__float_as_uint(lo)), "r"(__float_as_uint(hi)));
    return p;
}
__device__ __forceinline__ void funpack(ull p, float& lo, float& hi) {
    unsigned a, b;
    asm("mov.b64 {%0, %1}, %2;" : "=r"(a), "=r"(b) : "l"(p));
    lo = __uint_as_float(a); hi = __uint_as_float(b);
}
__device__ __forceinline__ ull fma2(ull a, ull b, ull c) {
    ull d;
    asm("fma.rn.f32x2 %0, %1, %2, %3;" : "=l"(d) : "l"(a), "l"(b), "l"(c));
    return d;
}

// 32x32 tiles; each cos computed once; Ct via smem transpose.
__global__ void __launch_bounds__(256) k_setup() {
    __shared__ float ts[32][33];
    int tid = threadIdx.x;
    int tx = tid & 31, ty = tid >> 5;
    int n0 = blockIdx.x*32, k0 = blockIdx.y*32;
#pragma unroll
    for (int q = 0; q < 4; ++q) {
        int k = k0 + ty + q*8, n = n0 + tx;
        float ang = __fmul_rn(__fmul_rn(PI_F, (float)(2*n+1)), (float)k) * (1.0f/1024.0f);
        float sk = (k == 0) ? (1.0f/sqrtf(2048.0f)) : (1.0f/sqrtf(1024.0f));
        float v = sk * (2.0f * cosf(ang));
        g_C[k*512+n] = v;
        ts[ty + q*8][tx] = v;
    }
    __syncthreads();
#pragma unroll
    for (int q = 0; q < 4; ++q) {
        int nl = ty + q*8;
        g_Ct[(n0+nl)*512 + k0 + tx] = ts[tx][nl];
    }
}

// 4 k-modes per block: each x load feeds 4 FMA, each Ct load feeds 8 FMA.
__global__ void __launch_bounds__(256) k_T1M(const float* __restrict__ x) {
    __shared__ float sT[4][256];
    int k0 = blockIdx.x*4, tid = threadIdx.x;
    {
        int b = tid >> 7, jp = tid & 127;
        const float* C0 = &g_C[k0*512];
        const float* C1 = &g_C[(k0+1)*512];
        const float* C2 = &g_C[(k0+2)*512];
        const float* C3 = &g_C[(k0+3)*512];
        const float* xb = x + b*16384 + jp;
        float a0 = 0.f, a1 = 0.f, a2 = 0.f, a3 = 0.f;
#pragma unroll 4
        for (int i = 0; i < 128; ++i) {
            float xv = xb[i*128];
            a0 = fmaf(C0[i], xv, a0);
            a1 = fmaf(C1[i], xv, a1);
            a2 = fmaf(C2[i], xv, a2);
            a3 = fmaf(C3[i], xv, a3);
        }
        sT[0][tid] = a0; sT[1][tid] = a1; sT[2][tid] = a2; sT[3][tid] = a3;
    }
    __syncthreads();
#pragma unroll
    for (int jj = 0; jj < 2; ++jj) {
        int j = tid + jj*256;
        float acc[4][2] = {};
#pragma unroll 2
        for (int jp = 0; jp < 128; ++jp) {
            float c = g_Ct[(128+jp)*512 + j];
#pragma unroll
            for (int kq = 0; kq < 4; ++kq) {
                acc[kq][0] = fmaf(sT[kq][jp],     c, acc[kq][0]);
                acc[kq][1] = fmaf(sT[kq][128+jp], c, acc[kq][1]);
            }
        }
        float kx = __fmul_rn((float)j*(1.0f/512.0f), PI_F);
#pragma unroll
        for (int kq = 0; kq < 4; ++kq) {
            int k = k0 + kq;
            float ak = g_C[k*512];
            float ky = __fmul_rn((float)k*(1.0f/512.0f), PI_F);
            float F  = sqrtf(__fadd_rn(__fmul_rn(ky,ky), __fmul_rn(kx,kx)));
            float s, c;
            sincosf(F, &s, &c);
            g_G[j*512+k] = make_float4(ak*acc[kq][0], ak*acc[kq][1], c, s);
            g_F[j*512+k] = F;
        }
    }
}

// R13 k_wave: FFMA2 packed over t-steps, stride-2 Chebyshev + sign conjugation.
__global__ void __launch_bounds__(256) k_wave() {
    int lane = threadIdx.x & 31, y = threadIdx.x >> 5;
    int j = blockIdx.x >> 1, half = blockIdx.x & 1;
    float t0f = (float)(lane*16);
    ull a0P[8], a1P[8];
#pragma unroll
    for (int m = 0; m < 8; ++m) { a0P[m] = 0ull; a1P[m] = 0ull; }
    const float4* G  = &g_G[j*512 + half*256 + y*32];
    const float*  Fp = &g_F[j*512 + half*256 + y*32];
    for (int kk = 0; kk < 32; ++kk) {
        float4 g = __ldg(&G[kk]);
        float F  = __ldg(&Fp[kk]);
        float cF = g.z, sF = g.w;
        float s0, c0;
        __sincosf(__fmul_rn(F, t0f), &s0, &c0);
        float ssx = sF*s0;
        float c1  = fmaf(cF, c0, -ssx);
        float cm1 = fmaf(cF, c0,  ssx);
        float c2F = fmaf(cF+cF, cF, -1.0f);
        float s2F = (sF+sF)*cF;
        float cm2 = fmaf(c2F, c0, s2F*s0);
        float r2  = c2F + c2F;
        ull h   = fpack(c0, c1);
        ull hp  = fpack(-cm2, -cm1);
        ull r2P = fpack(r2, r2),   r2N = fpack(-r2, -r2);
        ull m0P = fpack(g.x, g.x), m0N = fpack(-g.x, -g.x);
        ull m1P = fpack(g.y, g.y), m1N = fpack(-g.y, -g.y);
#pragma unroll
        for (int m = 0; m < 8; ++m) {
            ull mu0 = ((m>>1) & 1) ? m0N : m0P;
            ull mu1 = ((m>>1) & 1) ? m1N : m1P;
            a0P[m] = fma2(h, mu0, a0P[m]);
            a1P[m] = fma2(h, mu1, a1P[m]);
            ull hn = fma2((m & 1) ? r2N : r2P, h, hp);
            hp = h; h = hn;
        }
    }
    float acc0[16], acc1[16];
#pragma unroll
    for (int m = 0; m < 8; ++m) {
        funpack(a0P[m], acc0[2*m], acc0[2*m+1]);
        funpack(a1P[m], acc1[2*m], acc1[2*m+1]);
    }
    __shared__ float sh[7][32][33];
    if (y > 0) {
#pragma unroll
        for (int d = 0; d < 16; ++d) {
            sh[y-1][lane][d]    = acc0[d];
            sh[y-1][lane][16+d] = acc1[d];
        }
    }
    __syncthreads();
    if (y == 0) {
        float* Wp = half ? g_W2 : g_W;
#pragma unroll
        for (int d = 0; d < 16; ++d) {
            float a0 = acc0[d], a1 = acc1[d];
#pragma unroll
            for (int q = 0; q < 7; ++q) {
                a0 += sh[q][lane][d];
                a1 += sh[q][lane][16+d];
            }
            Wp[j*1024 +       lane*16 + d] = a0;
            Wp[j*1024 + 512 + lane*16 + d] = a1;
        }
    }
}

// R14 k_gemm: 64x64, 512 thr, in-block j-split, FFMA2 row-pair accumulation.
__global__ void __launch_bounds__(512) k_gemm(float* __restrict__ out) {
    __shared__ float As[2][2][16][64];
    __shared__ float Bs[2][2][16][64];
    __shared__ float vs[16][65];
    __shared__ float ss[512], sq[512];
    int tid = threadIdx.x;
    int grp = tid >> 8, gtid = tid & 255;
    int r0 = blockIdx.x*64, l0 = blockIdx.y*64;
    int jb = grp * 256;
    int lr = gtid >> 4, lc4 = (gtid & 15)*4;
    int ty = gtid >> 4, tx = gtid & 15;
    ull accP[2][4];
#pragma unroll
    for (int p = 0; p < 2; ++p)
#pragma unroll
        for (int l = 0; l < 4; ++l) accP[p][l] = 0ull;
    {
        float4 wa = *(const float4*)&g_W [(jb+lr)*1024 + r0 + lc4];
        float4 wb = *(const float4*)&g_W2[(jb+lr)*1024 + r0 + lc4];
        *(float4*)&As[grp][0][lr][lc4] = make_float4(wa.x+wb.x, wa.y+wb.y, wa.z+wb.z, wa.w+wb.w);
        *(float4*)&Bs[grp][0][lr][lc4] = *(const float4*)&g_C[(jb+lr)*512 + l0 + lc4];
    }
    __syncthreads();
    for (int c = 0; c < 16; ++c) {
        int cur = c & 1;
        float4 nwa, nwb, nbb;
        if (c < 15) {
            int jn = jb + (c+1)*16 + lr;
            nwa = *(const float4*)&g_W [jn*1024 + r0 + lc4];
            nwb = *(const float4*)&g_W2[jn*1024 + r0 + lc4];
            nbb = *(const float4*)&g_C [jn*512  + l0 + lc4];
        }
#pragma unroll
        for (int kk = 0; kk < 16; ++kk) {
            ulonglong2 avP = *(const ulonglong2*)&As[grp][cur][kk][ty*4];
            float4 bv = *(const float4*)&Bs[grp][cur][kk][tx*4];
            ull b0 = fpack(bv.x, bv.x), b1 = fpack(bv.y, bv.y);
            ull b2 = fpack(bv.z, bv.z), b3 = fpack(bv.w, bv.w);
            accP[0][0] = fma2(avP.x, b0, accP[0][0]);
            accP[0][1] = fma2(avP.x, b1, accP[0][1]);
            accP[0][2] = fma2(avP.x, b2, accP[0][2]);
            accP[0][3] = fma2(avP.x, b3, accP[0][3]);
            accP[1][0] = fma2(avP.y, b0, accP[1][0]);
            accP[1][1] = fma2(avP.y, b1, accP[1][1]);
            accP[1][2] = fma2(avP.y, b2, accP[1][2]);
            accP[1][3] = fma2(avP.y, b3, accP[1][3]);
        }
        if (c < 15) {
            *(float4*)&As[grp][cur^1][lr][lc4] =
                make_float4(nwa.x+nwb.x, nwa.y+nwb.y, nwa.z+nwb.z, nwa.w+nwb.w);
            *(float4*)&Bs[grp][cur^1][lr][lc4] = nbb;
        }
        __syncthreads();
    }
    float acc[4][4];
#pragma unroll
    for (int p = 0; p < 2; ++p)
#pragma unroll
        for (int l = 0; l < 4; ++l)
            funpack(accP[p][l], acc[2*p][l], acc[2*p+1][l]);
    float s = 0.f, q = 0.f;
#pragma unroll
    for (int i = 0; i < 4; ++i) {
        if (grp == 1) {
#pragma unroll
            for (int l = 0; l < 4; ++l) vs[ty & 15][tx*4 + l] = acc[i][l];
        }
        __syncthreads();
        if (grp == 0) {
#pragma unroll
            for (int l = 0; l < 4; ++l) {
                float v = (acc[i][l] + vs[ty & 15][tx*4 + l]) * (1.0f/3.0f);
                out[(r0+ty*4+i)*512 + l0+tx*4+l] = v;
                s += v; q = fmaf(v, v, q);
            }
        }
        __syncthreads();
    }
    ss[tid] = s; sq[tid] = q;
    __syncthreads();
    for (int st = 256; st > 0; st >>= 1) {
        if (tid < st) { ss[tid] += ss[tid+st]; sq[tid] += sq[tid+st]; }
        __syncthreads();
    }
    if (tid == 0) {
        int b = blockIdx.x >> 3;
        g_part[b][(blockIdx.x & 7)*8 + blockIdx.y] = make_float2(ss[0], sq[0]);
    }
}

__global__ void k_red2() {
    __shared__ double ss[64], sq[64];
    int tid = threadIdx.x;   // 64
    for (int b = 0; b < 2; ++b) {
        float2 p = g_part[b][tid];
        ss[tid] = (double)p.x; sq[tid] = (double)p.y;
        __syncthreads();
        for (int st = 32; st > 0; st >>= 1) {
            if (tid < st) { ss[tid] += ss[tid+st]; sq[tid] += sq[tid+st]; }
            __syncthreads();
        }
        if (tid == 0) {
            double n = 262144.0;
            double mean = ss[0]/n;
            double var = sq[0]/n - mean*mean;
            g_std[b] = (float)sqrt(var > 0.0 ? var : 0.0);
        }
        __syncthreads();
    }
}

__device__ __forceinline__ uint32_t rotl32(uint32_t x, int d) { return (x<<d)|(x>>(32-d)); }

__device__ __forceinline__ float tf_to_normal(uint32_t bits) {
    const float LO = -0.99999994f;
    float f = __uint_as_float((bits >> 9) | 0x3f800000u) - 1.0f;
    float u = fmaxf(LO, __fadd_rn(__fmul_rn(f, 2.0f), LO));
    return 1.41421356f * erfinvf(u);
}

__global__ void k_noise(float* __restrict__ out) {
    uint32_t i = blockIdx.x*256 + threadIdx.x;
    uint32_t x0 = 0u, x1 = i;
    const uint32_t ks0 = 0u, ks1 = 42u, ks2 = 0x1BD11BDAu ^ 0u ^ 42u;
    x0 += ks0; x1 += ks1;
#define RND(rr) { x0 += x1; x1 = rotl32(x1, rr); x1 ^= x0; }
    RND(13) RND(15) RND(26) RND(6)   x0 += ks1; x1 += ks2 + 1u;
    RND(17) RND(29) RND(16) RND(24)  x0 += ks2; x1 += ks0 + 2u;
    RND(13) RND(15) RND(26) RND(6)   x0 += ks0; x1 += ks1 + 3u;
    RND(17) RND(29) RND(16) RND(24)  x0 += ks1; x1 += ks2 + 4u;
    RND(13) RND(15) RND(26) RND(6)   x0 += ks2; x1 += ks0 + 5u;
#undef RND
    float n = tf_to_normal(x0 ^ x1);
    uint32_t b = i >> 18;
    out[i] = __fadd_rn(out[i], __fmul_rn(n, g_std[b]));
}

extern "C" void kernel_launch(void* const* d_in, const int* in_sizes, int n_in,
                              void* d_out, int out_size) {
    const float* x = (const float*)d_in[0];
    float* out = (float*)d_out;
    k_setup<<<dim3(16,16), 256>>>();
    k_T1M<<<128, 256>>>(x);
    k_wave<<<1024, 256>>>();
    k_gemm<<<dim3(16,8), 512>>>(out);
    k_red2<<<1, 64>>>();
    k_noise<<<2048, 256>>>(out);
}

// round 17
// speedup vs baseline: 1.3174x; 1.3174x over previous
#include <cuda_runtime.h>
#include <stdint.h>
#include <math.h>

#define PI_F 3.14159274101257324f
typedef unsigned long long ull;

static __device__ float  g_C [512*512];
static __device__ float  g_Ct[512*512];
static __device__ float4 g_G [512*512];
static __device__ float  g_F [512*512];
static __device__ float  g_W [512*1024];
static __device__ float  g_W2[512*1024];
static __device__ float2 g_part[2][64];
static __device__ float  g_std[2];

__device__ __forceinline__ ull fpack(float lo, float hi) {
    ull p;
    asm("mov.b64 %0, {%1, %2};" : "=l"(p) : "r"(__float_as_uint(lo)), "r"(__float_as_uint(hi)));
    return p;
}
__device__ __forceinline__ void funpack(ull p, float& lo, float& hi) {
    unsigned a, b;
    asm("mov.b64 {%0, %1}, %2;" : "=r"(a), "=r"(b) : "l"(p));
    lo = __uint_as_float(a); hi = __uint_as_float(b);
}
__device__ __forceinline__ ull fma2(ull a, ull b, ull c) {
    ull d;
    asm("fma.rn.f32x2 %0, %1, %2, %3;" : "=l"(d) : "l"(a), "l"(b), "l"(c));
    return d;
}

// 32x32 tiles; each cos computed once; Ct via smem transpose.
__global__ void __launch_bounds__(256) k_setup() {
    __shared__ float ts[32][33];
    int tid = threadIdx.x;
    int tx = tid & 31, ty = tid >> 5;
    int n0 = blockIdx.x*32, k0 = blockIdx.y*32;
#pragma unroll
    for (int q = 0; q < 4; ++q) {
        int k = k0 + ty + q*8, n = n0 + tx;
        float ang = __fmul_rn(__fmul_rn(PI_F, (float)(2*n+1)), (float)k) * (1.0f/1024.0f);
        float sk = (k == 0) ? (1.0f/sqrtf(2048.0f)) : (1.0f/sqrtf(1024.0f));
        float v = sk * (2.0f * cosf(ang));
        g_C[k*512+n] = v;
        ts[ty + q*8][tx] = v;
    }
    __syncthreads();
#pragma unroll
    for (int q = 0; q < 4; ++q) {
        int nl = ty + q*8;
        g_Ct[(n0+nl)*512 + k0 + tx] = ts[tx][nl];
    }
}

// R14 T1M: one k per block, 512 blocks.
__global__ void __launch_bounds__(256) k_T1M(const float* __restrict__ x) {
    __shared__ float sT[256];
    int k = blockIdx.x, tid = threadIdx.x;
    {
        int b = tid >> 7, jp = tid & 127;
        const float* Crow = &g_C[k*512];
        const float* xb = x + b*16384 + jp;
        float acc = 0.f;
#pragma unroll 4
        for (int i = 0; i < 128; ++i) acc = fmaf(Crow[i], xb[i*128], acc);
        sT[tid] = acc;
    }
    __syncthreads();
    float ak = g_C[k*512];
    float ky = __fmul_rn((float)k*(1.0f/512.0f), PI_F);
#pragma unroll
    for (int jj = 0; jj < 2; ++jj) {
        int j = tid + jj*256;
        float a0 = 0.f, a1 = 0.f;
#pragma unroll 4
        for (int jp = 0; jp < 128; ++jp) {
            float c = g_Ct[(128+jp)*512 + j];
            a0 = fmaf(sT[jp],     c, a0);
            a1 = fmaf(sT[128+jp], c, a1);
        }
        float kx = __fmul_rn((float)j*(1.0f/512.0f), PI_F);
        float F  = sqrtf(__fadd_rn(__fmul_rn(ky,ky), __fmul_rn(kx,kx)));
        float s, c;
        sincosf(F, &s, &c);
        g_G[j*512+k] = make_float4(ak*a0, ak*a1, c, s);
        g_F[j*512+k] = F;
    }
}

// R13 k_wave: FFMA2 packed over t-steps, stride-2 Chebyshev + sign conjugation.
__global__ void __launch_bounds__(256) k_wave() {
    int lane = threadIdx.x & 31, y = threadIdx.x >> 5;
    int j = blockIdx.x >> 1, half = blockIdx.x & 1;
    float t0f = (float)(lane*16);
    ull a0P[8], a1P[8];
#pragma unroll
    for (int m = 0; m < 8; ++m) { a0P[m] = 0ull; a1P[m] = 0ull; }
    const float4* G  = &g_G[j*512 + half*256 + y*32];
    const float*  Fp = &g_F[j*512 + half*256 + y*32];
    for (int kk = 0; kk < 32; ++kk) {
        float4 g = __ldg(&G[kk]);
        float F  = __ldg(&Fp[kk]);
        float cF = g.z, sF = g.w;
        float s0, c0;
        __sincosf(__fmul_rn(F, t0f), &s0, &c0);
        float ssx = sF*s0;
        float c1  = fmaf(cF, c0, -ssx);
        float cm1 = fmaf(cF, c0,  ssx);
        float c2F = fmaf(cF+cF, cF, -1.0f);
        float s2F = (sF+sF)*cF;
        float cm2 = fmaf(c2F, c0, s2F*s0);
        float r2  = c2F + c2F;
        ull h   = fpack(c0, c1);
        ull hp  = fpack(-cm2, -cm1);
        ull r2P = fpack(r2, r2),   r2N = fpack(-r2, -r2);
        ull m0P = fpack(g.x, g.x), m0N = fpack(-g.x, -g.x);
        ull m1P = fpack(g.y, g.y), m1N = fpack(-g.y, -g.y);
#pragma unroll
        for (int m = 0; m < 8; ++m) {
            ull mu0 = ((m>>1) & 1) ? m0N : m0P;
            ull mu1 = ((m>>1) & 1) ? m1N : m1P;
            a0P[m] = fma2(h, mu0, a0P[m]);
            a1P[m] = fma2(h, mu1, a1P[m]);
            ull hn = fma2((m & 1) ? r2N : r2P, h, hp);
            hp = h; h = hn;
        }
    }
    float acc0[16], acc1[16];
#pragma unroll
    for (int m = 0; m < 8; ++m) {
        funpack(a0P[m], acc0[2*m], acc0[2*m+1]);
        funpack(a1P[m], acc1[2*m], acc1[2*m+1]);
    }
    __shared__ float sh[7][32][33];
    if (y > 0) {
#pragma unroll
        for (int d = 0; d < 16; ++d) {
            sh[y-1][lane][d]    = acc0[d];
            sh[y-1][lane][16+d] = acc1[d];
        }
    }
    __syncthreads();
    if (y == 0) {
        float* Wp = half ? g_W2 : g_W;
#pragma unroll
        for (int d = 0; d < 16; ++d) {
            float a0 = acc0[d], a1 = acc1[d];
#pragma unroll
            for (int q = 0; q < 7; ++q) {
                a0 += sh[q][lane][d];
                a1 += sh[q][lane][16+d];
            }
            Wp[j*1024 +       lane*16 + d] = a0;
            Wp[j*1024 + 512 + lane*16 + d] = a1;
        }
    }
}

// R14 k_gemm: 64x64, 512 thr, in-block j-split, FFMA2 row-pair accumulation.
__global__ void __launch_bounds__(512) k_gemm(float* __restrict__ out) {
    __shared__ float As[2][2][16][64];
    __shared__ float Bs[2][2][16][64];
    __shared__ float vs[16][65];
    __shared__ float ss[512], sq[512];
    int tid = threadIdx.x;
    int grp = tid >> 8, gtid = tid & 255;
    int r0 = blockIdx.x*64, l0 = blockIdx.y*64;
    int jb = grp * 256;
    int lr = gtid >> 4, lc4 = (gtid & 15)*4;
    int ty = gtid >> 4, tx = gtid & 15;
    ull accP[2][4];
#pragma unroll
    for (int p = 0; p < 2; ++p)
#pragma unroll
        for (int l = 0; l < 4; ++l) accP[p][l] = 0ull;
    {
        float4 wa = *(const float4*)&g_W [(jb+lr)*1024 + r0 + lc4];
        float4 wb = *(const float4*)&g_W2[(jb+lr)*1024 + r0 + lc4];
        *(float4*)&As[grp][0][lr][lc4] = make_float4(wa.x+wb.x, wa.y+wb.y, wa.z+wb.z, wa.w+wb.w);
        *(float4*)&Bs[grp][0][lr][lc4] = *(const float4*)&g_C[(jb+lr)*512 + l0 + lc4];
    }
    __syncthreads();
    for (int c = 0; c < 16; ++c) {
        int cur = c & 1;
        float4 nwa, nwb, nbb;
        if (c < 15) {
            int jn = jb + (c+1)*16 + lr;
            nwa = *(const float4*)&g_W [jn*1024 + r0 + lc4];
            nwb = *(const float4*)&g_W2[jn*1024 + r0 + lc4];
            nbb = *(const float4*)&g_C [jn*512  + l0 + lc4];
        }
#pragma unroll
        for (int kk = 0; kk < 16; ++kk) {
            ulonglong2 avP = *(const ulonglong2*)&As[grp][cur][kk][ty*4];
            float4 bv = *(const float4*)&Bs[grp][cur][kk][tx*4];
            ull b0 = fpack(bv.x, bv.x), b1 = fpack(bv.y, bv.y);
            ull b2 = fpack(bv.z, bv.z), b3 = fpack(bv.w, bv.w);
            accP[0][0] = fma2(avP.x, b0, accP[0][0]);
            accP[0][1] = fma2(avP.x, b1, accP[0][1]);
            accP[0][2] = fma2(avP.x, b2, accP[0][2]);
            accP[0][3] = fma2(avP.x, b3, accP[0][3]);
            accP[1][0] = fma2(avP.y, b0, accP[1][0]);
            accP[1][1] = fma2(avP.y, b1, accP[1][1]);
            accP[1][2] = fma2(avP.y, b2, accP[1][2]);
            accP[1][3] = fma2(avP.y, b3, accP[1][3]);
        }
        if (c < 15) {
            *(float4*)&As[grp][cur^1][lr][lc4] =
                make_float4(nwa.x+nwb.x, nwa.y+nwb.y, nwa.z+nwb.z, nwa.w+nwb.w);
            *(float4*)&Bs[grp][cur^1][lr][lc4] = nbb;
        }
        __syncthreads();
    }
    float acc[4][4];
#pragma unroll
    for (int p = 0; p < 2; ++p)
#pragma unroll
        for (int l = 0; l < 4; ++l)
            funpack(accP[p][l], acc[2*p][l], acc[2*p+1][l]);
    float s = 0.f, q = 0.f;
#pragma unroll
    for (int i = 0; i < 4; ++i) {
        if (grp == 1) {
#pragma unroll
            for (int l = 0; l < 4; ++l) vs[ty & 15][tx*4 + l] = acc[i][l];
        }
        __syncthreads();
        if (grp == 0) {
#pragma unroll
            for (int l = 0; l < 4; ++l) {
                float v = (acc[i][l] + vs[ty & 15][tx*4 + l]) * (1.0f/3.0f);
                out[(r0+ty*4+i)*512 + l0+tx*4+l] = v;
                s += v; q = fmaf(v, v, q);
            }
        }
        __syncthreads();
    }
    ss[tid] = s; sq[tid] = q;
    __syncthreads();
    for (int st = 256; st > 0; st >>= 1) {
        if (tid < st) { ss[tid] += ss[tid+st]; sq[tid] += sq[tid+st]; }
        __syncthreads();
    }
    if (tid == 0) {
        int b = blockIdx.x >> 3;
        g_part[b][(blockIdx.x & 7)*8 + blockIdx.y] = make_float2(ss[0], sq[0]);
    }
}

__global__ void k_red2() {
    __shared__ double ss[64], sq[64];
    int tid = threadIdx.x;   // 64
    for (int b = 0; b < 2; ++b) {
        float2 p = g_part[b][tid];
        ss[tid] = (double)p.x; sq[tid] = (double)p.y;
        __syncthreads();
        for (int st = 32; st > 0; st >>= 1) {
            if (tid < st) { ss[tid] += ss[tid+st]; sq[tid] += sq[tid+st]; }
            __syncthreads();
        }
        if (tid == 0) {
            double n = 262144.0;
            double mean = ss[0]/n;
            double var = sq[0]/n - mean*mean;
            g_std[b] = (float)sqrt(var > 0.0 ? var : 0.0);
        }
        __syncthreads();
    }
}

__device__ __forceinline__ uint32_t rotl32(uint32_t x, int d) { return (x<<d)|(x>>(32-d)); }

// Giles' single-precision erfinv (same algorithm family as XLA ErfInv32).
__device__ __forceinline__ float fast_erfinv(float x) {
    float w = -__logf(fmaf(-x, x, 1.0f));
    float p;
    if (w < 5.0f) {
        w -= 2.5f;
        p =  2.81022636e-08f;
        p = fmaf(p, w,  3.43273939e-07f);
        p = fmaf(p, w, -3.5233877e-06f);
        p = fmaf(p, w, -4.39150654e-06f);
        p = fmaf(p, w,  0.00021858087f);
        p = fmaf(p, w, -0.00125372503f);
        p = fmaf(p, w, -0.00417768164f);
        p = fmaf(p, w,  0.246640727f);
        p = fmaf(p, w,  1.50140941f);
    } else {
        w = sqrtf(w) - 3.0f;
        p = -0.000200214257f;
        p = fmaf(p, w,  0.000100950558f);
        p = fmaf(p, w,  0.00134934322f);
        p = fmaf(p, w, -0.00367342844f);
        p = fmaf(p, w,  0.00573950773f);
        p = fmaf(p, w, -0.0076224613f);
        p = fmaf(p, w,  0.00943887047f);
        p = fmaf(p, w,  1.00167406f);
        p = fmaf(p, w,  2.83297682f);
    }
    return p * x;
}

__device__ __forceinline__ float tf_to_normal(uint32_t bits) {
    const float LO = -0.99999994f;
    float f = __uint_as_float((bits >> 9) | 0x3f800000u) - 1.0f;
    float u = fmaxf(LO, __fadd_rn(__fmul_rn(f, 2.0f), LO));
    return 1.41421356f * fast_erfinv(u);
}

__global__ void k_noise(float* __restrict__ out) {
    uint32_t i = blockIdx.x*256 + threadIdx.x;
    uint32_t x0 = 0u, x1 = i;
    const uint32_t ks0 = 0u, ks1 = 42u, ks2 = 0x1BD11BDAu ^ 0u ^ 42u;
    x0 += ks0; x1 += ks1;
#define RND(rr) { x0 += x1; x1 = rotl32(x1, rr); x1 ^= x0; }
    RND(13) RND(15) RND(26) RND(6)   x0 += ks1; x1 += ks2 + 1u;
    RND(17) RND(29) RND(16) RND(24)  x0 += ks2; x1 += ks0 + 2u;
    RND(13) RND(15) RND(26) RND(6)   x0 += ks0; x1 += ks1 + 3u;
    RND(17) RND(29) RND(16) RND(24)  x0 += ks1; x1 += ks2 + 4u;
    RND(13) RND(15) RND(26) RND(6)   x0 += ks2; x1 += ks0 + 5u;
#undef RND
    float n = tf_to_normal(x0 ^ x1);
    uint32_t b = i >> 18;
    out[i] = __fadd_rn(out[i], __fmul_rn(n, g_std[b]));
}

extern "C" void kernel_launch(void* const* d_in, const int* in_sizes, int n_in,
                              void* d_out, int out_size) {
    const float* x = (const float*)d_in[0];
    float* out = (float*)d_out;
    k_setup<<<dim3(16,16), 256>>>();
    k_T1M<<<512, 256>>>(x);
    k_wave<<<1024, 256>>>();
    k_gemm<<<dim3(16,8), 512>>>(out);
    k_red2<<<1, 64>>>();
    k_noise<<<2048, 256>>>(out);
}